// round 17
// baseline (speedup 1.0000x reference)
#include <cuda_runtime.h>
#include <cuda_fp16.h>
#include <cstdint>

namespace {

constexpr int kB = 2, kH = 16, kS = 2048, kDH = 64, kD = 1024;
constexpr int BQ = 128;             // Q rows per CTA (16 per warp, 8 warps)
constexpr int BN = 128;             // keys per tile (2 halves of 64)
constexpr int NITER = kS / BN;      // 16
// p' = exp2(s_raw * 0.125 * log2(e))  (re-centered: fixed shift cancels in softmax)
constexpr float C1 = 0.18033688011112042f;

constexpr int KPAD = 72;            // smem row stride in halves (pad 64 -> 72)
constexpr int NBUF = 2;             // double buffer, one barrier per 128-key tile

constexpr uint32_t TILE_B   = (uint32_t)BN * KPAD * 2;   // 18432 B per tile buffer
constexpr uint32_t SMEM_TOT = NBUF * TILE_B * 2;         // 73728 B (K + V)

__device__ __half   g_Qh[(size_t)kB * kH * kS * kDH];
__device__ __half   g_Kh[(size_t)kB * kH * kS * kDH];
__device__ __half   g_Vh[(size_t)kB * kH * kS * kDH];
__device__ unsigned g_mbits[(size_t)kB * kS * (kS / 32)];

// ---------------- PTX helpers (baseline ISA only) ----------------
__device__ __forceinline__ uint32_t smem_u32(const void* p) {
    uint32_t a;
    asm("{ .reg .u64 t; cvta.to.shared.u64 t, %1; cvt.u32.u64 %0, t; }" : "=r"(a) : "l"(p));
    return a;
}

__device__ __forceinline__ void cpa16(uint32_t dst, const void* src) {
    asm volatile("cp.async.cg.shared.global [%0], [%1], 16;" :: "r"(dst), "l"(src));
}
__device__ __forceinline__ void cpa_commit() {
    asm volatile("cp.async.commit_group;" ::: "memory");
}
template <int N>
__device__ __forceinline__ void cpa_wait() {
    asm volatile("cp.async.wait_group %0;" :: "n"(N) : "memory");
}

#define LDSM_X4(r0, r1, r2, r3, addr) \
    asm volatile("ldmatrix.sync.aligned.m8n8.x4.shared.b16 {%0,%1,%2,%3}, [%4];" \
        : "=r"(r0), "=r"(r1), "=r"(r2), "=r"(r3) : "r"(addr))

#define LDSM_X4_T(r0, r1, r2, r3, addr) \
    asm volatile("ldmatrix.sync.aligned.m8n8.x4.trans.shared.b16 {%0,%1,%2,%3}, [%4];" \
        : "=r"(r0), "=r"(r1), "=r"(r2), "=r"(r3) : "r"(addr))

#define MMA16816(d, a, b0, b1) \
    asm volatile("mma.sync.aligned.m16n8k16.row.col.f32.f16.f16.f32 " \
        "{%0,%1,%2,%3}, {%4,%5,%6,%7}, {%8,%9}, {%0,%1,%2,%3};" \
        : "+f"((d)[0]), "+f"((d)[1]), "+f"((d)[2]), "+f"((d)[3]) \
        : "r"((a)[0]), "r"((a)[1]), "r"((a)[2]), "r"((a)[3]), "r"(b0), "r"(b1))

__device__ __forceinline__ uint32_t ex2h2(uint32_t x) {
    uint32_t r;
    asm("ex2.approx.f16x2 %0, %1;" : "=r"(r) : "r"(x));
    return r;
}

// -------- merged pre-pass: cvt (blocks [0, NT_CVT)) + maskpack (rest) --------
constexpr int NT_CVT_BLOCKS = (3 * (kB * kS * kD / 8)) / 256;   // 6144
constexpr int MASK_BLOCKS   = (kB * kS * kS) / 256;             // 32768

__global__ void prep_kernel(const float* __restrict__ Q, const float* __restrict__ K,
                            const float* __restrict__ V, const int* __restrict__ M) {
    if (blockIdx.x < NT_CVT_BLOCKS) {
        const int nt = kB * kS * kD / 8;
        int t = blockIdx.x * 256 + threadIdx.x;
        const float* src;
        __half* dst;
        if (t < nt)          { src = Q; dst = g_Qh; }
        else if (t < 2 * nt) { src = K; dst = g_Kh; t -= nt; }
        else                 { src = V; dst = g_Vh; t -= 2 * nt; }

        const int i8 = t * 8;
        const int b  = i8 >> 21;
        const int s  = (i8 >> 10) & (kS - 1);
        const int hd = i8 & (kD - 1);
        const int h  = hd >> 6, d0 = hd & 63;

        float4 f0 = *reinterpret_cast<const float4*>(src + i8);
        float4 f1 = *reinterpret_cast<const float4*>(src + i8 + 4);
        __half2 h0 = __floats2half2_rn(f0.x, f0.y);
        __half2 h1 = __floats2half2_rn(f0.z, f0.w);
        __half2 h2 = __floats2half2_rn(f1.x, f1.y);
        __half2 h3 = __floats2half2_rn(f1.z, f1.w);
        uint4 o;
        o.x = *reinterpret_cast<const uint32_t*>(&h0);
        o.y = *reinterpret_cast<const uint32_t*>(&h1);
        o.z = *reinterpret_cast<const uint32_t*>(&h2);
        o.w = *reinterpret_cast<const uint32_t*>(&h3);
        *reinterpret_cast<uint4*>(dst + ((((size_t)b * kH + h) * kS + s) * kDH + d0)) = o;
    } else {
        const unsigned gid = (blockIdx.x - NT_CVT_BLOCKS) * 256 + threadIdx.x;
        const int v = M[gid] != 0;
        const unsigned bal = __ballot_sync(0xffffffffu, v);
        if ((threadIdx.x & 31) == 0) g_mbits[gid >> 5] = bal;
    }
}

// ============================ main attention kernel ============================
// 256 threads, 8 warps x 16 Q-rows. 128-key tiles (one barrier per tile),
// processed as two 64-key halves to hold register pressure at the 128 cap.
__global__ __launch_bounds__(256, 2)
void mha_mma_kernel(float* __restrict__ Out) {
    extern __shared__ __align__(16) uint8_t smem[];
    // layout: [K buf0][K buf1][V buf0][V buf1], each TILE_B bytes

    const int tid  = threadIdx.x;
    const int w    = tid >> 5;          // 0..7
    const int lane = tid & 31;
    const int gid  = lane >> 2;
    const int tig  = lane & 3;
    const int q0 = blockIdx.x * BQ;
    const int h  = blockIdx.y;
    const int b  = blockIdx.z;

    const size_t headoff = (((size_t)b * kH + h) * kS) * kDH;
    const __half* Qh = g_Qh + headoff;
    const __half* Kh = g_Kh + headoff;
    const __half* Vh = g_Vh + headoff;

    const uint32_t smem_base = smem_u32(smem);
    const uint32_t kArr = smem_base;                    // K buffers
    const uint32_t vArr = smem_base + NBUF * TILE_B;    // V buffers

    // ---- Q A-fragments: ONE 16-row block per warp ----
    const int rowA = q0 + w * 16 + gid;
    uint32_t qf[4][4];
    #pragma unroll
    for (int t = 0; t < 4; ++t) {
        const int dlo = t * 16 + 2 * tig;
        qf[t][0] = *reinterpret_cast<const uint32_t*>(Qh + (size_t)rowA * kDH + dlo);
        qf[t][1] = *reinterpret_cast<const uint32_t*>(Qh + (size_t)(rowA + 8) * kDH + dlo);
        qf[t][2] = *reinterpret_cast<const uint32_t*>(Qh + (size_t)rowA * kDH + dlo + 8);
        qf[t][3] = *reinterpret_cast<const uint32_t*>(Qh + (size_t)(rowA + 8) * kDH + dlo + 8);
    }

    const unsigned* mlo_p = g_mbits + ((size_t)b * kS + rowA) * (kS / 32);
    const unsigned* mhi_p = g_mbits + ((size_t)b * kS + rowA + 8) * (kS / 32);

    const int keyG1 = (lane & 7) + ((lane >> 4) & 1) * 8;   // GEMM1 (K, non-trans)
    const int dG1   = ((lane >> 3) & 1) * 8;
    const int keyG2 = (lane & 7) + ((lane >> 3) & 1) * 8;   // GEMM2 (V, trans)
    const int dG2   = ((lane >> 4) & 1) * 8;

    // staging: 256 threads, 128 rows -> each thread half a row (32 halves) of K and V
    const int ldKey = tid >> 1;          // 0..127
    const int ldD   = (tid & 1) * 32;    // 0, 32

    auto stage_tile = [&](int buf, int k0) {
        const __half* ksrc = Kh + (size_t)(k0 + ldKey) * kDH + ldD;
        const __half* vsrc = Vh + (size_t)(k0 + ldKey) * kDH + ldD;
        const uint32_t kdst = kArr + buf * TILE_B + ((uint32_t)ldKey * KPAD + ldD) * 2;
        const uint32_t vdst = vArr + buf * TILE_B + ((uint32_t)ldKey * KPAD + ldD) * 2;
        #pragma unroll
        for (int i = 0; i < 4; ++i) {
            cpa16(kdst + i * 16, ksrc + i * 8);
            cpa16(vdst + i * 16, vsrc + i * 8);
        }
    };

    float o[8][4];
    #pragma unroll
    for (int j = 0; j < 8; ++j)
        #pragma unroll
        for (int c = 0; c < 4; ++c) o[j][c] = 0.0f;
    float l_lo = 0.0f, l_hi = 0.0f;

    stage_tile(0, 0);
    cpa_commit();

    const float NINF = __int_as_float(0xff800000);   // -inf: fp16 exp -> 0

    for (int it = 0; it < NITER; ++it) {
        const int bufi = it & 1;

        cpa_wait<0>();       // tile it resident
        __syncthreads();     // ONE barrier per 128-key tile

        if (it + 1 < NITER) {          // prefetch next tile into the other buffer
            stage_tile(bufi ^ 1, (it + 1) * BN);
            cpa_commit();
        }

        // mask words for this 128-key tile (L2-resident; ~1.5k cyc slack to use)
        const uint4 m4l = *reinterpret_cast<const uint4*>(mlo_p + it * 4);
        const uint4 m4h = *reinterpret_cast<const uint4*>(mhi_p + it * 4);
        const unsigned mwl[4] = { m4l.x, m4l.y, m4l.z, m4l.w };
        const unsigned mwh[4] = { m4h.x, m4h.y, m4h.z, m4h.w };

        const uint32_t kbase = kArr + bufi * TILE_B;
        const uint32_t vbase = vArr + bufi * TILE_B;

        // ==== two 64-key halves: GEMM1 -> softmax -> GEMM2 per half ====
        #pragma unroll
        for (int hf = 0; hf < 2; ++hf) {
            const int krow0 = hf * 64;

            // ---- GEMM1 whole-half, t-outer: 8 independent accumulator chains ----
            float s[8][4];
            #pragma unroll
            for (int j = 0; j < 8; ++j)
                #pragma unroll
                for (int c = 0; c < 4; ++c) s[j][c] = 0.0f;

            #pragma unroll
            for (int t = 0; t < 4; ++t) {
                #pragma unroll
                for (int np = 0; np < 4; ++np) {
                    uint32_t r0, r1, r2, r3;
                    const uint32_t addr = kbase +
                        (((uint32_t)(krow0 + np * 16 + keyG1)) * KPAD +
                         (uint32_t)(t * 16 + dG1)) * 2;
                    LDSM_X4(r0, r1, r2, r3, addr);
                    MMA16816(s[2 * np],     qf[t], r0, r1);
                    MMA16816(s[2 * np + 1], qf[t], r2, r3);
                }
            }

            // ---- softmax: x = s*C1, mask-select to -inf, fp16 pack, f16x2 ex2 ----
            __half2 ls_lo = __float2half2_rn(0.0f), ls_hi = ls_lo;
            uint32_t pf[4][4];
            #pragma unroll
            for (int j = 0; j < 8; ++j) {
                const int wsel  = 2 * hf + (j >> 2);      // compile-time
                const int bbase = (8 * j) % 32 + 2 * tig;
                const unsigned wl = mwl[wsel];
                const unsigned wh = mwh[wsel];
                float x0 = s[j][0] * C1;
                float x1 = s[j][1] * C1;
                float x2 = s[j][2] * C1;
                float x3 = s[j][3] * C1;
                x0 = ((wl >> bbase) & 1u)       ? x0 : NINF;
                x1 = ((wl >> (bbase + 1)) & 1u) ? x1 : NINF;
                x2 = ((wh >> bbase) & 1u)       ? x2 : NINF;
                x3 = ((wh >> (bbase + 1)) & 1u) ? x3 : NINF;
                __half2 a01 = __floats2half2_rn(x0, x1);
                __half2 a23 = __floats2half2_rn(x2, x3);
                uint32_t e01 = ex2h2(*reinterpret_cast<const uint32_t*>(&a01));
                uint32_t e23 = ex2h2(*reinterpret_cast<const uint32_t*>(&a23));
                pf[j >> 1][(j & 1) * 2 + 0] = e01;
                pf[j >> 1][(j & 1) * 2 + 1] = e23;
                ls_lo = __hadd2(ls_lo, *reinterpret_cast<const __half2*>(&e01));
                ls_hi = __hadd2(ls_hi, *reinterpret_cast<const __half2*>(&e23));
            }
            // flush per-half (64-key) half2 sums into fp32 totals (same cadence as R15)
            l_lo += __low2float(ls_lo) + __high2float(ls_lo);
            l_hi += __low2float(ls_hi) + __high2float(ls_hi);

            // ---- GEMM2: O += P_half x V[half keys][all d] ----
            #pragma unroll
            for (int t = 0; t < 4; ++t) {
                #pragma unroll
                for (int np = 0; np < 4; ++np) {
                    uint32_t r0, r1, r2, r3;
                    const uint32_t addr = vbase +
                        (((uint32_t)(krow0 + t * 16 + keyG2)) * KPAD +
                         (uint32_t)(np * 16 + dG2)) * 2;
                    LDSM_X4_T(r0, r1, r2, r3, addr);
                    MMA16816(o[2 * np],     pf[t], r0, r1);
                    MMA16816(o[2 * np + 1], pf[t], r2, r3);
                }
            }
        }
    }

    // ---- row-sum reduce across the 4 lanes sharing each row ----
    #pragma unroll
    for (int off = 1; off <= 2; off <<= 1) {
        l_lo += __shfl_xor_sync(0xffffffffu, l_lo, off);
        l_hi += __shfl_xor_sync(0xffffffffu, l_hi, off);
    }
    const float il = 1.0f / l_lo, ih = 1.0f / l_hi;

    // ---- write out (2 rows per thread) ----
    float* plo = Out + ((size_t)b * kS + rowA) * kD + h * kDH;
    float* phi = Out + ((size_t)b * kS + rowA + 8) * kD + h * kDH;
    #pragma unroll
    for (int j = 0; j < 8; ++j) {
        const int col = 8 * j + 2 * tig;
        *reinterpret_cast<float2*>(plo + col) = make_float2(o[j][0] * il, o[j][1] * il);
        *reinterpret_cast<float2*>(phi + col) = make_float2(o[j][2] * ih, o[j][3] * ih);
    }
}

} // namespace

extern "C" void kernel_launch(void* const* d_in, const int* in_sizes, int n_in,
                              void* d_out, int out_size) {
    const float* q = (const float*)d_in[0];
    const float* k = (const float*)d_in[1];
    const float* v = (const float*)d_in[2];
    const int*   m = (const int*)d_in[3];
    float* out = (float*)d_out;

    // allow 72KB dynamic smem (host-side attribute; not a stream op -> capture-safe)
    cudaFuncSetAttribute(mha_mma_kernel,
                         cudaFuncAttributeMaxDynamicSharedMemorySize, SMEM_TOT);

    prep_kernel<<<NT_CVT_BLOCKS + MASK_BLOCKS, 256>>>(q, k, v, m);

    dim3 grid(kS / BQ, kH, kB);   // 16 x 16 x 2 = 512 CTAs (256 threads each)
    mha_mma_kernel<<<grid, 256, SMEM_TOT>>>(out);
}